// round 4
// baseline (speedup 1.0000x reference)
#include <cuda_runtime.h>

// hybrid_position_embedding: reference ends with softmax over a SINGLETON axis
//   hmap = hybrid[:, None, :]   # (B, 1, N)
//   out  = softmax(hmap, axis=1) == 1.0 exactly (hybrid is finite via the
//   int32 round-trip, so x - max(x) == 0 elementwise).
// Output is identically 1.0f, input-independent. Verified rel_err = 0.0 in
// rounds 1-3.
//
// R1-R3 sweep (256x256 / 128x512 / 64x1024): kernel 3.49-3.74us invariant to
// grid shape, issue <=9%, DRAM 0% -- confirmed at the fixed per-launch ramp
// floor (~T_ovh 5000cyc + ~1us graph-replay). Data movement (1MB) is ~0.1us.
// Final config: 256 CTAs x 256 threads (best measured kernel time, R1) with
// the guard-free exact-store body (one STG.128/thread, no ISETP).

__global__ void __launch_bounds__(256) fill_ones_exact(float4* __restrict__ out) {
    out[blockIdx.x * 256 + threadIdx.x] = make_float4(1.0f, 1.0f, 1.0f, 1.0f);
}

__global__ void __launch_bounds__(256) fill_ones_guarded(float* __restrict__ out, int n) {
    int i4 = (blockIdx.x * 256 + threadIdx.x) * 4;
    if (i4 + 3 < n) {
        *reinterpret_cast<float4*>(out + i4) = make_float4(1.0f, 1.0f, 1.0f, 1.0f);
    } else {
        for (int j = i4; j < n; ++j) out[j] = 1.0f;
    }
}

extern "C" void kernel_launch(void* const* d_in, const int* in_sizes, int n_in,
                              void* d_out, int out_size) {
    (void)d_in; (void)in_sizes; (void)n_in;

    // Fast path: out_size divides exactly into 256-thread CTAs of float4
    // stores (true here: 262144 floats = 65536 float4 = 256 CTAs x 256 thr).
    if ((out_size & 3) == 0 && ((out_size >> 2) & 255) == 0) {
        int blocks = (out_size >> 2) >> 8;    // 256
        fill_ones_exact<<<blocks, 256>>>((float4*)d_out);
    } else {
        int n_vec4 = (out_size + 3) >> 2;
        int blocks = (n_vec4 + 255) / 256;
        fill_ones_guarded<<<blocks, 256>>>((float*)d_out, out_size);
    }
}